// round 4
// baseline (speedup 1.0000x reference)
#include <cuda_runtime.h>

#define B_SZ   2048
#define T_LEN  256
#define E_DIM  50
#define H_DIM  50
#define G_DIM  200   // 4H
#define KP     52    // padded row (13 * float4)
#define BPC    14    // batches per CTA
#define NTA    416   // 13 warps; 400 active gate threads
#define GRID_A 147   // ceil(2048/14)
#define ITEMS  (BPC * 50)   // 700 (bl, q) work items

__device__ __forceinline__ float sigmoidf_(float x) {
    return __fdividef(1.f, 1.f + __expf(-x));
}
__device__ __forceinline__ float tanhf_(float x) {
    float ax = fabsf(x);
    float e  = __expf(-2.f * ax);
    float r  = __fdividef(1.f - e, 1.f + e);
    return copysignf(r, x);
}

// 13-float4 dot product of two padded-52 rows (pads are zero)
__device__ __forceinline__ float dot52(const float* __restrict__ a,
                                       const float* __restrict__ b) {
    const float4* av = (const float4*)a;
    const float4* bv = (const float4*)b;
    float r0 = 0.f, r1 = 0.f, r2 = 0.f, r3 = 0.f;
    #pragma unroll
    for (int p = 0; p < 13; p++) {
        float4 x = av[p], y = bv[p];
        r0 = fmaf(x.x, y.x, r0);
        r1 = fmaf(x.y, y.y, r1);
        r2 = fmaf(x.z, y.z, r2);
        r3 = fmaf(x.w, y.w, r3);
    }
    return (r0 + r1) + (r2 + r3);
}

// Named-register weight load (strided global, coalesced across g)
#define LDW(k) const float w##k = wb[(k) * G_DIM];
// One float4 of src against 4 named weight regs
#define GS(p, A, Bq, C, D) { float4 v = sv[p]; \
    a0 = fmaf(v.x, w##A,  a0); a1 = fmaf(v.y, w##Bq, a1); \
    a2 = fmaf(v.z, w##C,  a2); a3 = fmaf(v.w, w##D,  a3); }

__global__ void __launch_bounds__(NTA, 1)
lstm_fused_all(const int* __restrict__ inp, const float* __restrict__ emb,
               const float* __restrict__ Wk, const float* __restrict__ Uk,
               const float* __restrict__ bias,
               const float* __restrict__ W1, const float* __restrict__ b1,
               const float* __restrict__ W2, const float* __restrict__ b2,
               float* __restrict__ out)
{
    __shared__ __align__(16) float xsh[2][BPC][KP];     // embedded inputs (dbl buf)
    __shared__ __align__(16) float hsh[BPC][KP];        // hidden state
    __shared__ __align__(16) float zpart[2][BPC][G_DIM];// gate partial sums
    __shared__ __align__(16) float w1ts[E_DIM][KP];     // w1ts[j][k] = W1[k][j]
    __shared__ __align__(16) float d1sh[BPC][KP];
    __shared__ __align__(16) float d2sh[BPC][KP];
    __shared__ __align__(16) float w2s[KP];
    __shared__ float b1s[E_DIM];
    __shared__ float b2sh;

    const int tid    = threadIdx.x;
    const int b0     = blockIdx.x * BPC;
    const bool active = (tid < 2 * G_DIM);
    const int role   = active ? (tid / G_DIM) : 0;   // 0: x@Wk, 1: h@Uk
    const int g      = active ? (tid % G_DIM) : 0;

    // Per-thread weight column (50 named scalar registers)
    const float* wb = (role ? Uk : Wk) + g;
    LDW(0)  LDW(1)  LDW(2)  LDW(3)  LDW(4)  LDW(5)  LDW(6)  LDW(7)  LDW(8)  LDW(9)
    LDW(10) LDW(11) LDW(12) LDW(13) LDW(14) LDW(15) LDW(16) LDW(17) LDW(18) LDW(19)
    LDW(20) LDW(21) LDW(22) LDW(23) LDW(24) LDW(25) LDW(26) LDW(27) LDW(28) LDW(29)
    LDW(30) LDW(31) LDW(32) LDW(33) LDW(34) LDW(35) LDW(36) LDW(37) LDW(38) LDW(39)
    LDW(40) LDW(41) LDW(42) LDW(43) LDW(44) LDW(45) LDW(46) LDW(47) LDW(48) LDW(49)
    const float bg = (active && role == 0) ? bias[g] : 0.f;

    // Zero all shared rows (pads stay zero forever)
    for (int i = tid; i < 2 * BPC * KP; i += NTA) (&xsh[0][0][0])[i] = 0.f;
    for (int i = tid; i < BPC * KP;     i += NTA) (&hsh[0][0])[i]    = 0.f;
    for (int i = tid; i < BPC * KP;     i += NTA) (&d1sh[0][0])[i]   = 0.f;
    for (int i = tid; i < BPC * KP;     i += NTA) (&d2sh[0][0])[i]   = 0.f;
    // Dense weights into shared (transposed, padded)
    for (int i = tid; i < E_DIM * KP; i += NTA) {
        int j = i / KP, k = i % KP;
        w1ts[j][k] = (k < H_DIM) ? W1[k * E_DIM + j] : 0.f;
    }
    for (int i = tid; i < KP; i += NTA) w2s[i] = (i < E_DIM) ? W2[i] : 0.f;
    if (tid < E_DIM) b1s[tid] = b1[tid];
    if (tid == 0)    b2sh = b2[0];
    __syncthreads();

    // Work-item mapping (shared by emb-prefetch / update / dense): (bl, q)
    const int  it0 = tid,        it1 = tid + NTA;
    const bool v0  = (it0 < ITEMS), v1 = (it1 < ITEMS);
    const int  bl0 = v0 ? (it0 / 50) : 0, q0 = v0 ? (it0 % 50) : 0;
    const int  bl1 = v1 ? (it1 / 50) : 0, q1 = v1 ? (it1 % 50) : 0;
    const bool sb0 = v0 && (b0 + bl0 < B_SZ);
    const bool sb1 = v1 && (b0 + bl1 < B_SZ);
    const int* ir0 = inp + (size_t)(sb0 ? (b0 + bl0) : 0) * T_LEN;
    const int* ir1 = inp + (size_t)(sb1 ? (b0 + bl1) : 0) * T_LEN;

    // Preload x(t=0)
    if (v0) xsh[0][bl0][q0] = sb0 ? emb[(size_t)ir0[0] * E_DIM + q0] : 0.f;
    if (v1) xsh[0][bl1][q1] = sb1 ? emb[(size_t)ir1[0] * E_DIM + q1] : 0.f;
    __syncthreads();

    float cst0 = 0.f, cst1 = 0.f;

    for (int t = 0; t < T_LEN; t++) {
        const int cur = t & 1, nxt = cur ^ 1;

        // Prefetch embeddings for t+1 (LDG latency hidden behind gate math)
        float pre0 = 0.f, pre1 = 0.f;
        if (t + 1 < T_LEN) {
            if (sb0) pre0 = emb[(size_t)ir0[t + 1] * E_DIM + q0];
            if (sb1) pre1 = emb[(size_t)ir1[t + 1] * E_DIM + q1];
        }

        // ---- Gate partials: zpart[role][bl][g] ----
        if (active) {
            #pragma unroll 1
            for (int bl = 0; bl < BPC; bl++) {
                const float4* sv = (const float4*)(role ? hsh[bl] : xsh[cur][bl]);
                float a0 = bg, a1 = 0.f, a2 = 0.f, a3 = 0.f;
                GS(0,  0, 1, 2, 3)    GS(1,  4, 5, 6, 7)    GS(2,  8, 9, 10, 11)
                GS(3, 12, 13, 14, 15) GS(4, 16, 17, 18, 19) GS(5, 20, 21, 22, 23)
                GS(6, 24, 25, 26, 27) GS(7, 28, 29, 30, 31) GS(8, 32, 33, 34, 35)
                GS(9, 36, 37, 38, 39) GS(10, 40, 41, 42, 43) GS(11, 44, 45, 46, 47)
                { float2 tv = *(const float2*)((const float*)sv + 48);
                  a0 = fmaf(tv.x, w48, a0); a1 = fmaf(tv.y, w49, a1); }
                zpart[role][bl][g] = (a0 + a1) + (a2 + a3);
            }
        }
        __syncthreads();

        // ---- State update (Keras order i,f,c,o) + commit prefetched x ----
        if (v0) {
            float zi = zpart[0][bl0][q0]           + zpart[1][bl0][q0];
            float zf = zpart[0][bl0][q0 +   H_DIM] + zpart[1][bl0][q0 +   H_DIM];
            float zg = zpart[0][bl0][q0 + 2*H_DIM] + zpart[1][bl0][q0 + 2*H_DIM];
            float zo = zpart[0][bl0][q0 + 3*H_DIM] + zpart[1][bl0][q0 + 3*H_DIM];
            float ig = sigmoidf_(zi), fg = sigmoidf_(zf);
            float gg = tanhf_(zg),    og = sigmoidf_(zo);
            cst0 = fg * cst0 + ig * gg;
            hsh[bl0][q0] = og * tanhf_(cst0);
            xsh[nxt][bl0][q0] = pre0;
        }
        if (v1) {
            float zi = zpart[0][bl1][q1]           + zpart[1][bl1][q1];
            float zf = zpart[0][bl1][q1 +   H_DIM] + zpart[1][bl1][q1 +   H_DIM];
            float zg = zpart[0][bl1][q1 + 2*H_DIM] + zpart[1][bl1][q1 + 2*H_DIM];
            float zo = zpart[0][bl1][q1 + 3*H_DIM] + zpart[1][bl1][q1 + 3*H_DIM];
            float ig = sigmoidf_(zi), fg = sigmoidf_(zf);
            float gg = tanhf_(zg),    og = sigmoidf_(zo);
            cst1 = fg * cst1 + ig * gg;
            hsh[bl1][q1] = og * tanhf_(cst1);
            xsh[nxt][bl1][q1] = pre1;
        }
        __syncthreads();

        // ---- Dense layer 1: d1 = relu(h @ W1 + b1) ----
        if (v0) d1sh[bl0][q0] = fmaxf(b1s[q0] + dot52(hsh[bl0], w1ts[q0]), 0.f);
        if (v1) d1sh[bl1][q1] = fmaxf(b1s[q1] + dot52(hsh[bl1], w1ts[q1]), 0.f);
        __syncthreads();

        // ---- Dense layer 2: d2 = relu(d1 @ W1 + b1) ----
        if (v0) d2sh[bl0][q0] = fmaxf(b1s[q0] + dot52(d1sh[bl0], w1ts[q0]), 0.f);
        if (v1) d2sh[bl1][q1] = fmaxf(b1s[q1] + dot52(d1sh[bl1], w1ts[q1]), 0.f);
        __syncthreads();

        // ---- Output: p[b][t] = sigmoid(d2 . W2 + b2) ----
        // (runs concurrently with next step's gate phase; d2sh next written
        //  three syncs from now)
        if (tid < BPC && b0 + tid < B_SZ) {
            float acc = b2sh + dot52(d2sh[tid], w2s);
            out[(size_t)(b0 + tid) * T_LEN + t] = sigmoidf_(acc);
        }
    }
}

// ---------------------------------------------------------------------------
extern "C" void kernel_launch(void* const* d_in, const int* in_sizes, int n_in,
                              void* d_out, int out_size)
{
    const int*   inp = (const int*)  d_in[0];
    const float* emb = (const float*)d_in[1];
    const float* Wk  = (const float*)d_in[2];
    const float* Uk  = (const float*)d_in[3];
    const float* b   = (const float*)d_in[4];
    const float* W1  = (const float*)d_in[5];
    const float* b1  = (const float*)d_in[6];
    const float* W2  = (const float*)d_in[7];
    const float* b2  = (const float*)d_in[8];
    float* out = (float*)d_out;

    lstm_fused_all<<<GRID_A, NTA>>>(inp, emb, Wk, Uk, b, W1, b1, W2, b2, out);
}